// round 13
// baseline (speedup 1.0000x reference)
#include <cuda_runtime.h>
#include <cuda_bf16.h>
#include <cstdint>

#define NN      8192
#define NODE    256
#define DEG     16
#define NFEAT   128
#define NHID    256
#define NCLASS  64

// ---------------- device scratch (no allocation allowed) --------------------
// bf16x2-packed hi/lo operand arrays (k-major words, 2 k per word)
__device__ uint32_t g_Xh [NN * 64];        // adj@x        [8192][64w]
__device__ uint32_t g_Xl [NN * 64];
__device__ uint32_t g_Hh [NN * 128];       // relu(gX@W1)  [8192][128w]
__device__ uint32_t g_Hl [NN * 128];
__device__ uint32_t g_W1h[NHID * 64];      // W1^T         [256][64w]
__device__ uint32_t g_W1l[NHID * 64];
__device__ uint32_t g_W2h[NCLASS * 128];   // W2^T         [64][128w]
__device__ uint32_t g_W2l[NCLASS * 128];
__device__ float    g_T  [NN * NCLASS];    // gH @ W2 (fp32 for agg_lsm)
__device__ unsigned g_keep[NN];

// pack two f32 -> bf16x2 (first arg = upper half)
__device__ __forceinline__ uint32_t bf2(float hi, float lo) {
    uint32_t r; asm("cvt.rn.bf16x2.f32 %0, %1, %2;" : "=r"(r) : "f"(hi), "f"(lo));
    return r;
}
// split float4 (4 consecutive k) into hi/lo bf16x2 word pairs
__device__ __forceinline__ void split4(float4 v, uint2& h, uint2& l) {
    h.x = bf2(v.y, v.x); h.y = bf2(v.w, v.z);
    float hx = __uint_as_float(h.x << 16), hy = __uint_as_float(h.x & 0xffff0000u);
    float hz = __uint_as_float(h.y << 16), hw = __uint_as_float(h.y & 0xffff0000u);
    l.x = bf2(v.y - hy, v.x - hx); l.y = bf2(v.w - hw, v.z - hz);
}
__device__ __forceinline__ void mma_bf16(float c[4], const uint32_t a[4], const uint32_t b[2]) {
    asm volatile(
        "mma.sync.aligned.m16n8k16.row.col.f32.bf16.bf16.f32 "
        "{%0,%1,%2,%3}, {%4,%5,%6,%7}, {%8,%9}, {%0,%1,%2,%3};"
        : "+f"(c[0]), "+f"(c[1]), "+f"(c[2]), "+f"(c[3])
        : "r"(a[0]), "r"(a[1]), "r"(a[2]), "r"(a[3]), "r"(b[0]), "r"(b[1]));
}

// Dynamic smem sizes for agg1
#define A1_SMX_FLT   (NODE * 32)
#define A1_EDGE_INT  (NODE * DEG)
#define A1_SMEM_B    ((A1_SMX_FLT + A1_EDGE_INT + NODE + NODE) * 4)

// ---------------------------------------------------------------------------
// K1: blocks 0..127 : agg1 — smem-staged adj @ x, emits SPLIT gXh/gXl.
//     Also writes dedup masks (g==0). blocks 128..175: W transposes (split).
// ---------------------------------------------------------------------------
__global__ __launch_bounds__(256)
void agg1_kernel(const float* __restrict__ x, const int* __restrict__ edge,
                 const float* __restrict__ W1, const float* __restrict__ W2,
                 uint32_t* __restrict__ gXh, uint32_t* __restrict__ gXl,
                 unsigned* __restrict__ keep_out,
                 uint32_t* __restrict__ W1h, uint32_t* __restrict__ W1l,
                 uint32_t* __restrict__ W2h, uint32_t* __restrict__ W2l)
{
    extern __shared__ float dyn[];
    const int bid = blockIdx.x;
    const int tid = threadIdx.x;

    if (bid < 128) {
        float*    smx   = dyn;                                           // [256][32]
        int*      sedge = reinterpret_cast<int*>(dyn + A1_SMX_FLT);      // [256][16]
        unsigned* smask = reinterpret_cast<unsigned*>(sedge + A1_EDGE_INT);

        const int blk  = bid >> 2;
        const int g    = bid & 3;
        const int base = blk * NODE;

#pragma unroll
        for (int i = tid; i < NODE * 8; i += 256) {
            int r = i >> 3, qd = i & 7;
            *reinterpret_cast<float4*>(&smx[r * 32 + qd * 4]) =
                *reinterpret_cast<const float4*>(
                    x + (size_t)(base + r) * NFEAT + g * 32 + qd * 4);
        }
        {
            const int4* ep = reinterpret_cast<const int4*>(edge + (size_t)(base + tid) * DEG);
            int4 v0 = ep[0], v1 = ep[1], v2 = ep[2], v3 = ep[3];
            int e[16] = {v0.x, v0.y, v0.z, v0.w, v1.x, v1.y, v1.z, v1.w,
                         v2.x, v2.y, v2.z, v2.w, v3.x, v3.y, v3.z, v3.w};
            unsigned mask = 0;
#pragma unroll
            for (int i = 0; i < 16; ++i) {
                bool keep = e[i] >= 0;
#pragma unroll
                for (int p = 0; p < i; ++p) keep = keep && (e[i] != e[p]);
                if (keep) mask |= 1u << i;
                sedge[tid * DEG + i] = (e[i] >= 0) ? e[i] : 0;
            }
            smask[tid] = mask;
            if (g == 0) keep_out[base + tid] = mask;
        }
        __syncthreads();

#pragma unroll
        for (int p = 0; p < 8; ++p) {
            const int nl = p * 32 + (tid >> 3);
            const int qd = tid & 7;
            const unsigned mask = smask[nl];
            float4 a = make_float4(0.f, 0.f, 0.f, 0.f);
#pragma unroll
            for (int t = 0; t < DEG; ++t) {
                int   j  = sedge[nl * DEG + t];
                float fm = (float)((mask >> t) & 1u);
                float4 v = *reinterpret_cast<const float4*>(&smx[j * 32 + qd * 4]);
                a.x = fmaf(v.x, fm, a.x);
                a.y = fmaf(v.y, fm, a.y);
                a.z = fmaf(v.z, fm, a.z);
                a.w = fmaf(v.w, fm, a.w);
            }
            uint2 h, l; split4(a, h, l);
            int w = (base + nl) * 64 + g * 16 + qd * 2;
            *reinterpret_cast<uint2*>(&gXh[w]) = h;
            *reinterpret_cast<uint2*>(&gXl[w]) = l;
        }
    } else {
        float* t = dyn;                         // [32][33]
        const float* src; uint32_t *dh, *dl; int C, KW2, tr, tc;
        if (bid < 160) { int b = bid - 128; src = W1; dh = W1h; dl = W1l; C = NHID;  KW2 = 64;  tr = b >> 3; tc = b & 7; }
        else           { int b = bid - 160; src = W2; dh = W2h; dl = W2l; C = NCLASS; KW2 = 128; tr = b >> 1; tc = b & 1; }
        const int r  = tid >> 3;
        const int fq = tid & 7;
        float4 v = *reinterpret_cast<const float4*>(src + (size_t)(tr * 32 + r) * C + tc * 32 + fq * 4);
        t[r * 33 + fq * 4 + 0] = v.x; t[r * 33 + fq * 4 + 1] = v.y;
        t[r * 33 + fq * 4 + 2] = v.z; t[r * 33 + fq * 4 + 3] = v.w;
        __syncthreads();
        float4 o;
        o.x = t[(fq * 4 + 0) * 33 + r]; o.y = t[(fq * 4 + 1) * 33 + r];
        o.z = t[(fq * 4 + 2) * 33 + r]; o.w = t[(fq * 4 + 3) * 33 + r];
        uint2 h, l; split4(o, h, l);
        int n = tc * 32 + r;
        int w = n * KW2 + tr * 16 + fq * 2;
        *reinterpret_cast<uint2*>(&dh[w]) = h;
        *reinterpret_cast<uint2*>(&dl[w]) = l;
    }
}

// ---------------------------------------------------------------------------
// bf16 mma.sync GEMM on pre-split hi/lo operands. Pure LDG->STS->HMMA loop.
// SPLIT: epilogue emits bf16x2 hi/lo (relu'd) for the next GEMM; else fp32.
// ---------------------------------------------------------------------------
template<int BM, int BN, int KTOT, int WM, int WN, bool RELU, bool SPLIT>
__global__ __launch_bounds__(256)
void gemm_bf16(const uint32_t* __restrict__ Ahg, const uint32_t* __restrict__ Alg,
               const uint32_t* __restrict__ Bhg, const uint32_t* __restrict__ Blg,
               float* __restrict__ Cf, uint32_t* __restrict__ Ch,
               uint32_t* __restrict__ Cl, int ldcw)
{
    constexpr int KW     = KTOT / 2;          // words per operand row
    constexpr int LW     = 20;                // smem row stride (16 + 4 pad)
    constexpr int NWN    = BN / WN;
    constexpr int MSUB   = WM / 16;
    constexpr int NSUB   = WN / 8;
    constexpr int NCHUNK = KTOT / 32;
    constexpr int A_W    = BM * LW;
    constexpr int B_W    = BN * LW;
    constexpr int STAGE_W = 2 * A_W + 2 * B_W;
    constexpr int AV     = BM * 4 / 256;      // uint4 per thread per chunk
    constexpr int BV     = BN * 4 / 256;

    extern __shared__ uint32_t smw[];

    const int tid   = threadIdx.x;
    const int wid   = tid >> 5;
    const int lane  = tid & 31;
    const int brow  = blockIdx.x * BM;
    const int bcol  = blockIdx.y * BN;
    const int warpM = (wid / NWN) * WM;
    const int warpN = (wid % NWN) * WN;
    const int grp   = lane >> 2;
    const int qk    = lane & 3;

    float acc[MSUB][NSUB][4] = {};
    uint4 pah[AV], pal[AV], pbh[BV], pbl[BV];

#pragma unroll
    for (int j = 0; j < AV; ++j) {
        int i = tid + j * 256, r = i >> 2, f = (i & 3) * 4;
        pah[j] = *reinterpret_cast<const uint4*>(&Ahg[(size_t)(brow + r) * KW + f]);
        pal[j] = *reinterpret_cast<const uint4*>(&Alg[(size_t)(brow + r) * KW + f]);
    }
#pragma unroll
    for (int j = 0; j < BV; ++j) {
        int i = tid + j * 256, r = i >> 2, f = (i & 3) * 4;
        pbh[j] = *reinterpret_cast<const uint4*>(&Bhg[(size_t)(bcol + r) * KW + f]);
        pbl[j] = *reinterpret_cast<const uint4*>(&Blg[(size_t)(bcol + r) * KW + f]);
    }

    for (int c = 0; c < NCHUNK; ++c) {
        uint32_t* Ah = smw + (c & 1) * STAGE_W;
        uint32_t* Al = Ah + A_W;
        uint32_t* Bh = Al + A_W;
        uint32_t* Bl = Bh + B_W;

#pragma unroll
        for (int j = 0; j < AV; ++j) {
            int i = tid + j * 256, r = i >> 2, f = (i & 3) * 4;
            *reinterpret_cast<uint4*>(&Ah[r * LW + f]) = pah[j];
            *reinterpret_cast<uint4*>(&Al[r * LW + f]) = pal[j];
        }
#pragma unroll
        for (int j = 0; j < BV; ++j) {
            int i = tid + j * 256, r = i >> 2, f = (i & 3) * 4;
            *reinterpret_cast<uint4*>(&Bh[r * LW + f]) = pbh[j];
            *reinterpret_cast<uint4*>(&Bl[r * LW + f]) = pbl[j];
        }
        if (c + 1 < NCHUNK) {
#pragma unroll
            for (int j = 0; j < AV; ++j) {
                int i = tid + j * 256, r = i >> 2, f = (i & 3) * 4;
                pah[j] = *reinterpret_cast<const uint4*>(&Ahg[(size_t)(brow + r) * KW + (c + 1) * 16 + f]);
                pal[j] = *reinterpret_cast<const uint4*>(&Alg[(size_t)(brow + r) * KW + (c + 1) * 16 + f]);
            }
#pragma unroll
            for (int j = 0; j < BV; ++j) {
                int i = tid + j * 256, r = i >> 2, f = (i & 3) * 4;
                pbh[j] = *reinterpret_cast<const uint4*>(&Bhg[(size_t)(bcol + r) * KW + (c + 1) * 16 + f]);
                pbl[j] = *reinterpret_cast<const uint4*>(&Blg[(size_t)(bcol + r) * KW + (c + 1) * 16 + f]);
            }
        }
        __syncthreads();

#pragma unroll
        for (int ks = 0; ks < 2; ++ks) {
            const int kw = ks * 8;
            uint32_t aH[MSUB][4], aL[MSUB][4];
#pragma unroll
            for (int ms = 0; ms < MSUB; ++ms) {
                int r0 = (warpM + ms * 16 + grp) * LW + kw + qk;
                int r1 = r0 + 8 * LW;
                aH[ms][0] = Ah[r0];     aH[ms][1] = Ah[r1];
                aH[ms][2] = Ah[r0 + 4]; aH[ms][3] = Ah[r1 + 4];
                aL[ms][0] = Al[r0];     aL[ms][1] = Al[r1];
                aL[ms][2] = Al[r0 + 4]; aL[ms][3] = Al[r1 + 4];
            }
            uint32_t bH[NSUB][2], bL[NSUB][2];
#pragma unroll
            for (int ns = 0; ns < NSUB; ++ns) {
                int b0 = (warpN + ns * 8 + grp) * LW + kw + qk;
                bH[ns][0] = Bh[b0]; bH[ns][1] = Bh[b0 + 4];
                bL[ns][0] = Bl[b0]; bL[ns][1] = Bl[b0 + 4];
            }
#pragma unroll
            for (int ms = 0; ms < MSUB; ++ms)
#pragma unroll
                for (int ns = 0; ns < NSUB; ++ns) {
                    mma_bf16(acc[ms][ns], aH[ms], bH[ns]);
                    mma_bf16(acc[ms][ns], aH[ms], bL[ns]);
                    mma_bf16(acc[ms][ns], aL[ms], bH[ns]);
                }
        }
        __syncthreads();
    }

#pragma unroll
    for (int ms = 0; ms < MSUB; ++ms)
#pragma unroll
        for (int ns = 0; ns < NSUB; ++ns) {
            int row = brow + warpM + ms * 16 + grp;
            int col = warpN + ns * 8 + 2 * qk;          // even, block-local
            float c0 = acc[ms][ns][0], c1 = acc[ms][ns][1];
            float c2 = acc[ms][ns][2], c3 = acc[ms][ns][3];
            if (RELU) {
                c0 = fmaxf(c0, 0.f); c1 = fmaxf(c1, 0.f);
                c2 = fmaxf(c2, 0.f); c3 = fmaxf(c3, 0.f);
            }
            if (SPLIT) {
                int w0 = row * ldcw + ((bcol + col) >> 1);
                uint32_t h = bf2(c1, c0);
                float hx = __uint_as_float(h << 16), hy = __uint_as_float(h & 0xffff0000u);
                Ch[w0] = h;
                Cl[w0] = bf2(c1 - hy, c0 - hx);
                int w1 = (row + 8) * ldcw + ((bcol + col) >> 1);
                uint32_t h2 = bf2(c3, c2);
                float hz = __uint_as_float(h2 << 16), hw = __uint_as_float(h2 & 0xffff0000u);
                Ch[w1] = h2;
                Cl[w1] = bf2(c3 - hw, c2 - hz);
            } else {
                *reinterpret_cast<float2*>(Cf + (size_t)row * ldcw + bcol + col) =
                    make_float2(c0, c1);
                *reinterpret_cast<float2*>(Cf + (size_t)(row + 8) * ldcw + bcol + col) =
                    make_float2(c2, c3);
            }
        }
}

// ---------------------------------------------------------------------------
// K4: agg2 + log_softmax (unchanged from R12 — branchless gather).
// ---------------------------------------------------------------------------
__global__ __launch_bounds__(256)
void agg_lsm_kernel(const float* __restrict__ T, const int* __restrict__ edge,
                    const unsigned* __restrict__ keep_in, float* __restrict__ out)
{
    const int node = (blockIdx.x * blockDim.x + threadIdx.x) >> 5;
    const int lane = threadIdx.x & 31;
    const int nbh  = lane >> 4;
    const int cq   = lane & 15;
    const int base = (node >> 8) << 8;

    int e = edge[node * DEG + cq];
    unsigned mask = keep_in[node];

    float4 a = make_float4(0.f, 0.f, 0.f, 0.f);
#pragma unroll
    for (int t = 0; t < 8; ++t) {
        int nb = 2 * t + nbh;
        int j  = __shfl_sync(0xffffffffu, e, nb);
        unsigned bit = (mask >> nb) & 1u;
        int jj = bit ? j : 0;
        float fm = (float)bit;
        float4 v = *reinterpret_cast<const float4*>(
            T + (size_t)(base + jj) * NCLASS + (cq << 2));
        a.x = fmaf(v.x, fm, a.x);
        a.y = fmaf(v.y, fm, a.y);
        a.z = fmaf(v.z, fm, a.z);
        a.w = fmaf(v.w, fm, a.w);
    }
    a.x += __shfl_xor_sync(0xffffffffu, a.x, 16);
    a.y += __shfl_xor_sync(0xffffffffu, a.y, 16);
    a.z += __shfl_xor_sync(0xffffffffu, a.z, 16);
    a.w += __shfl_xor_sync(0xffffffffu, a.w, 16);

    float mx = fmaxf(fmaxf(a.x, a.y), fmaxf(a.z, a.w));
#pragma unroll
    for (int o = 8; o; o >>= 1)
        mx = fmaxf(mx, __shfl_xor_sync(0xffffffffu, mx, o));
    float s = expf(a.x - mx) + expf(a.y - mx) + expf(a.z - mx) + expf(a.w - mx);
#pragma unroll
    for (int o = 8; o; o >>= 1)
        s += __shfl_xor_sync(0xffffffffu, s, o);
    float lse = logf(s) + mx;

    if (lane < 16)
        *reinterpret_cast<float4*>(out + (size_t)node * NCLASS + (cq << 2)) =
            make_float4(a.x - lse, a.y - lse, a.z - lse, a.w - lse);
}

// ---------------------------------------------------------------------------
extern "C" void kernel_launch(void* const* d_in, const int* in_sizes, int n_in,
                              void* d_out, int out_size)
{
    const float* x    = (const float*)d_in[0];
    const int*   edge = (const int*)  d_in[1];
    const float* W1   = (const float*)d_in[2];
    const float* W2   = (const float*)d_in[3];
    float* out = (float*)d_out;

    uint32_t *gXh, *gXl, *gHh, *gHl, *gW1h, *gW1l, *gW2h, *gW2l;
    float *gT;
    unsigned *gK;
    cudaGetSymbolAddress((void**)&gXh,  g_Xh);
    cudaGetSymbolAddress((void**)&gXl,  g_Xl);
    cudaGetSymbolAddress((void**)&gHh,  g_Hh);
    cudaGetSymbolAddress((void**)&gHl,  g_Hl);
    cudaGetSymbolAddress((void**)&gW1h, g_W1h);
    cudaGetSymbolAddress((void**)&gW1l, g_W1l);
    cudaGetSymbolAddress((void**)&gW2h, g_W2h);
    cudaGetSymbolAddress((void**)&gW2l, g_W2l);
    cudaGetSymbolAddress((void**)&gT,   g_T);
    cudaGetSymbolAddress((void**)&gK,   g_keep);

    constexpr int SMEM1 = 2 * (2 * 128 + 2 * 128) * 20 * 4;   // 81920
    constexpr int SMEM2 = 2 * (2 * 64 + 2 * 64) * 20 * 4;     // 40960
    cudaFuncSetAttribute(agg1_kernel,
                         cudaFuncAttributeMaxDynamicSharedMemorySize, A1_SMEM_B);
    cudaFuncSetAttribute(gemm_bf16<128, 128, 128, 64, 32, true, true>,
                         cudaFuncAttributeMaxDynamicSharedMemorySize, SMEM1);
    cudaFuncSetAttribute(gemm_bf16<64, 64, 256, 32, 16, false, false>,
                         cudaFuncAttributeMaxDynamicSharedMemorySize, SMEM2);

    // K1: gXh/gXl = split(adj @ x), keep masks, split W transposes
    agg1_kernel<<<176, 256, A1_SMEM_B>>>(x, edge, W1, W2,
                                         gXh, gXl, gK, gW1h, gW1l, gW2h, gW2l);
    // K2: gHh/gHl = split(relu(gX @ W1))   [ldcw = NHID/2 = 128 words]
    gemm_bf16<128, 128, 128, 64, 32, true, true>
        <<<dim3(64, 2), 256, SMEM1>>>(gXh, gXl, gW1h, gW1l, nullptr, gHh, gHl, 128);
    // K3: gT = gH @ W2 (fp32 out)          [ldcw = NCLASS = 64 floats]
    gemm_bf16<64, 64, 256, 32, 16, false, false>
        <<<dim3(128, 1), 256, SMEM2>>>(gHh, gHl, gW2h, gW2l, gT, nullptr, nullptr, 64);
    // K4: out = log_softmax(adj @ gT)
    agg_lsm_kernel<<<NN / 8, 256>>>(gT, edge, gK, out);
}